// round 6
// baseline (speedup 1.0000x reference)
#include <cuda_runtime.h>
#include <math.h>

// One CTA per row, single pass over DRAM each way.
// Phase A: stream row (float4), pool pairs + inline noise, stage pooled row in
//          SMEM, accumulate sum/sumsq.  Block reduce -> mu, 1/sd.
// Phase B: read SMEM (float4), write normalized duplicated pairs (2x STG.128).
__global__ __launch_bounds__(1024, 1)
void fused_kernel(const float* __restrict__ x,
                  const float* __restrict__ noise,
                  const int*   __restrict__ move_p,
                  float*       __restrict__ out,
                  int L) {
    extern __shared__ float s_pool[];          // halfL floats + 66 reduction slots
    const int halfL = L >> 1;
    float* s_red = s_pool + halfL;

    const int row = blockIdx.x;
    const float* __restrict__ xrow = x + (size_t)row * (size_t)L;
    float*       __restrict__ orow = out + (size_t)row * (size_t)L;

    int mv = __ldg(move_p);
    mv %= L; if (mv < 0) mv += L;
    const bool aligned_mv = ((mv & 3) == 0);   // x float4 path needs s0 % 4 == 0

    const int ngroups = halfL >> 2;            // groups of 4 pooled values
    float sum = 0.0f, sumsq = 0.0f;

    // ---- Phase A ----
    #pragma unroll 2
    for (int g = threadIdx.x; g < ngroups; g += blockDim.x) {
        const int j0 = g << 2;                 // first pooled index of group
        const int s0 = (j0 << 1) - mv;         // x offset of first element
        float p0, p1, p2, p3;
        if (aligned_mv && s0 >= 0 && s0 + 7 < L) {
            // 32B of x + 32B of noise per group, all LDG.128
            float4 a  = *reinterpret_cast<const float4*>(xrow + s0);
            float4 b  = *reinterpret_cast<const float4*>(xrow + s0 + 4);
            float4 n0 = *reinterpret_cast<const float4*>(noise + (j0 << 1));
            float4 n1 = *reinterpret_cast<const float4*>(noise + (j0 << 1) + 4);
            p0 = (a.x + a.y) * 0.5f + (n0.x + n0.y) * 0.02f;
            p1 = (a.z + a.w) * 0.5f + (n0.z + n0.w) * 0.02f;
            p2 = (b.x + b.y) * 0.5f + (n1.x + n1.y) * 0.02f;
            p3 = (b.z + b.w) * 0.5f + (n1.z + n1.w) * 0.02f;
        } else {
            float p[4];
            #pragma unroll
            for (int k = 0; k < 4; k++) {
                int s = s0 + 2 * k;
                if (s < 0) s += L; else if (s >= L) s -= L;
                int s1 = s + 1; if (s1 >= L) s1 -= L;
                int j = j0 + k;
                p[k] = (xrow[s] + xrow[s1]) * 0.5f
                     + (noise[2 * j] + noise[2 * j + 1]) * 0.02f;
            }
            p0 = p[0]; p1 = p[1]; p2 = p[2]; p3 = p[3];
        }
        float4 pv; pv.x = p0; pv.y = p1; pv.z = p2; pv.w = p3;
        *reinterpret_cast<float4*>(s_pool + j0) = pv;     // STS.128
        sum   += (p0 + p1) + (p2 + p3);
        sumsq += (p0 * p0 + p1 * p1) + (p2 * p2 + p3 * p3);
    }
    // Tail (halfL not divisible by 4)
    for (int j = (ngroups << 2) + threadIdx.x; j < halfL; j += blockDim.x) {
        int s = 2 * j - mv;
        if (s < 0) s += L; else if (s >= L) s -= L;
        int s1 = s + 1; if (s1 >= L) s1 -= L;
        float p = (xrow[s] + xrow[s1]) * 0.5f
                + (noise[2 * j] + noise[2 * j + 1]) * 0.02f;
        s_pool[j] = p;
        sum += p; sumsq += p * p;
    }

    // ---- Block reduction ----
    #pragma unroll
    for (int o = 16; o > 0; o >>= 1) {
        sum   += __shfl_down_sync(0xFFFFFFFFu, sum,   o);
        sumsq += __shfl_down_sync(0xFFFFFFFFu, sumsq, o);
    }
    const int wid  = threadIdx.x >> 5;
    const int lane = threadIdx.x & 31;
    const int nwarps = blockDim.x >> 5;
    if (lane == 0) { s_red[wid] = sum; s_red[32 + wid] = sumsq; }
    __syncthreads();
    if (threadIdx.x < 32) {
        float s2 = (threadIdx.x < nwarps) ? s_red[threadIdx.x]      : 0.0f;
        float q2 = (threadIdx.x < nwarps) ? s_red[32 + threadIdx.x] : 0.0f;
        #pragma unroll
        for (int o = 16; o > 0; o >>= 1) {
            s2 += __shfl_down_sync(0xFFFFFFFFu, s2, o);
            q2 += __shfl_down_sync(0xFFFFFFFFu, q2, o);
        }
        if (threadIdx.x == 0) {
            float inv_n = 1.0f / (float)halfL;
            float mu    = s2 * inv_n;
            float var   = fmaxf(q2 * inv_n - mu * mu, 0.0f);
            s_red[64] = mu;
            s_red[65] = rsqrtf(var);
        }
    }
    __syncthreads();
    const float mu     = s_red[64];
    const float inv_sd = s_red[65];

    // ---- Phase B: LDS.128 + 2x STG.128 per group ----
    #pragma unroll 2
    for (int g = threadIdx.x; g < ngroups; g += blockDim.x) {
        const int j0 = g << 2;
        float4 p = *reinterpret_cast<const float4*>(s_pool + j0);
        float v0 = (p.x - mu) * inv_sd;
        float v1 = (p.y - mu) * inv_sd;
        float v2 = (p.z - mu) * inv_sd;
        float v3 = (p.w - mu) * inv_sd;
        float4 w0; w0.x = v0; w0.y = v0; w0.z = v1; w0.w = v1;
        float4 w1; w1.x = v2; w1.y = v2; w1.z = v3; w1.w = v3;
        *reinterpret_cast<float4*>(orow + (j0 << 1))     = w0;
        *reinterpret_cast<float4*>(orow + (j0 << 1) + 4) = w1;
    }
    for (int j = (ngroups << 2) + threadIdx.x; j < halfL; j += blockDim.x) {
        float v = (s_pool[j] - mu) * inv_sd;
        orow[2 * j]     = v;
        orow[2 * j + 1] = v;
    }
}

extern "C" void kernel_launch(void* const* d_in, const int* in_sizes, int n_in,
                              void* d_out, int out_size) {
    const float* x     = (const float*)d_in[0];
    const float* noise = (const float*)d_in[1];
    const int*   move  = (const int*)d_in[2];
    float*       out   = (float*)d_out;

    const int L = in_sizes[1];               // 100000
    const int B = in_sizes[0] / L;           // 512
    const int halfL = L / 2;

    size_t smem = (size_t)halfL * sizeof(float) + 66 * sizeof(float);
    cudaFuncSetAttribute(fused_kernel,
                         cudaFuncAttributeMaxDynamicSharedMemorySize,
                         (int)smem);
    fused_kernel<<<B, 1024, smem>>>(x, noise, move, out, L);
}

// round 7
// speedup vs baseline: 1.0091x; 1.0091x over previous
#include <cuda_runtime.h>
#include <math.h>

// Precomputed row-invariant pooled-noise term: (noise[2j]+noise[2j+1])*STD/2.
// 200 KB -> L2-resident across all 512 row-CTAs.
#define MAX_POOL 65536
__device__ float g_npool[MAX_POOL];

__global__ void npool_kernel(const float* __restrict__ noise, int halfL) {
    int j = blockIdx.x * blockDim.x + threadIdx.x;
    if (j < halfL)
        g_npool[j] = (noise[2 * j] + noise[2 * j + 1]) * 0.02f;  // STD=0.04, /2
}

// One CTA per row; pooled row staged in SMEM; single DRAM pass each way.
__global__ __launch_bounds__(1024, 1)
void fused_kernel(const float* __restrict__ x,
                  const int*   __restrict__ move_p,
                  float*       __restrict__ out,
                  int L) {
    extern __shared__ float s_pool[];          // halfL floats + 66 reduction slots
    const int halfL = L >> 1;
    float* s_red = s_pool + halfL;

    const int row = blockIdx.x;
    const float* __restrict__ xrow = x + (size_t)row * (size_t)L;
    float*       __restrict__ orow = out + (size_t)row * (size_t)L;

    int mv = __ldg(move_p);
    mv %= L; if (mv < 0) mv += L;

    const int ngroups = halfL >> 2;            // groups of 4 pooled values
    const int tid = threadIdx.x, bs = blockDim.x;

    // Fast-path group interval [glo, ghi): s0 = 8g - mv must satisfy
    // s0 >= 0, s0+7 <= L-1, and 16B alignment (mv % 4 == 0).
    int glo, ghi;
    if ((mv & 3) == 0) {
        glo = (mv + 7) >> 3;
        if (glo > ngroups) glo = ngroups;
        ghi = (L + mv - 8) / 8 + 1;
        if (ghi > ngroups) ghi = ngroups;
        if (ghi < glo)     ghi = glo;
    } else {
        glo = 0; ghi = 0;                      // everything via scalar path
    }

    float sum = 0.0f, sumsq = 0.0f;

    // ---- scalar edges (wrap region; tiny for small mv) ----
    for (int e = tid; e < glo + (ngroups - ghi); e += bs) {
        int g = (e < glo) ? e : (ghi + (e - glo));
        int j0 = g << 2;
        #pragma unroll
        for (int k = 0; k < 4; k++) {
            int j = j0 + k;
            int s = 2 * j - mv;
            if (s < 0) s += L; else if (s >= L) s -= L;
            int s1 = s + 1; if (s1 >= L) s1 -= L;
            float p = (xrow[s] + xrow[s1]) * 0.5f + g_npool[j];
            s_pool[j] = p;
            sum += p; sumsq = fmaf(p, p, sumsq);
        }
    }
    // tail j (halfL % 4 != 0)
    for (int j = (ngroups << 2) + tid; j < halfL; j += bs) {
        int s = 2 * j - mv;
        if (s < 0) s += L; else if (s >= L) s -= L;
        int s1 = s + 1; if (s1 >= L) s1 -= L;
        float p = (xrow[s] + xrow[s1]) * 0.5f + g_npool[j];
        s_pool[j] = p;
        sum += p; sumsq = fmaf(p, p, sumsq);
    }

    // ---- branch-free hot loop: 3x LDG.128 + STS.128 per group ----
    #pragma unroll 4
    for (int g = glo + tid; g < ghi; g += bs) {
        const int j0 = g << 2;
        const int s0 = (g << 3) - mv;
        float4 a  = __ldcs(reinterpret_cast<const float4*>(xrow + s0));
        float4 b  = __ldcs(reinterpret_cast<const float4*>(xrow + s0 + 4));
        float4 np = *reinterpret_cast<const float4*>(g_npool + j0);
        float4 pv;
        pv.x = (a.x + a.y) * 0.5f + np.x;
        pv.y = (a.z + a.w) * 0.5f + np.y;
        pv.z = (b.x + b.y) * 0.5f + np.z;
        pv.w = (b.z + b.w) * 0.5f + np.w;
        *reinterpret_cast<float4*>(s_pool + j0) = pv;
        sum   += (pv.x + pv.y) + (pv.z + pv.w);
        sumsq  = fmaf(pv.x, pv.x, sumsq);
        sumsq  = fmaf(pv.y, pv.y, sumsq);
        sumsq  = fmaf(pv.z, pv.z, sumsq);
        sumsq  = fmaf(pv.w, pv.w, sumsq);
    }

    // ---- block reduction of (sum, sumsq) ----
    #pragma unroll
    for (int o = 16; o > 0; o >>= 1) {
        sum   += __shfl_down_sync(0xFFFFFFFFu, sum,   o);
        sumsq += __shfl_down_sync(0xFFFFFFFFu, sumsq, o);
    }
    const int wid  = tid >> 5;
    const int lane = tid & 31;
    const int nwarps = bs >> 5;
    if (lane == 0) { s_red[wid] = sum; s_red[32 + wid] = sumsq; }
    __syncthreads();
    if (tid < 32) {
        float s2 = (tid < nwarps) ? s_red[tid]      : 0.0f;
        float q2 = (tid < nwarps) ? s_red[32 + tid] : 0.0f;
        #pragma unroll
        for (int o = 16; o > 0; o >>= 1) {
            s2 += __shfl_down_sync(0xFFFFFFFFu, s2, o);
            q2 += __shfl_down_sync(0xFFFFFFFFu, q2, o);
        }
        if (tid == 0) {
            float inv_n = 1.0f / (float)halfL;
            float mu    = s2 * inv_n;
            float var   = fmaxf(q2 * inv_n - mu * mu, 0.0f);
            s_red[64] = mu;
            s_red[65] = rsqrtf(var);
        }
    }
    __syncthreads();
    const float mu     = s_red[64];
    const float inv_sd = s_red[65];

    // ---- Phase B: LDS.128 + 2x streaming STG.128 per group ----
    #pragma unroll 4
    for (int g = tid; g < ngroups; g += bs) {
        const int j0 = g << 2;
        float4 p = *reinterpret_cast<const float4*>(s_pool + j0);
        float v0 = (p.x - mu) * inv_sd;
        float v1 = (p.y - mu) * inv_sd;
        float v2 = (p.z - mu) * inv_sd;
        float v3 = (p.w - mu) * inv_sd;
        float4 w0; w0.x = v0; w0.y = v0; w0.z = v1; w0.w = v1;
        float4 w1; w1.x = v2; w1.y = v2; w1.z = v3; w1.w = v3;
        __stcs(reinterpret_cast<float4*>(orow + (j0 << 1)),     w0);
        __stcs(reinterpret_cast<float4*>(orow + (j0 << 1) + 4), w1);
    }
    for (int j = (ngroups << 2) + tid; j < halfL; j += bs) {
        float v = (s_pool[j] - mu) * inv_sd;
        orow[2 * j]     = v;
        orow[2 * j + 1] = v;
    }
}

extern "C" void kernel_launch(void* const* d_in, const int* in_sizes, int n_in,
                              void* d_out, int out_size) {
    const float* x     = (const float*)d_in[0];
    const float* noise = (const float*)d_in[1];
    const int*   move  = (const int*)d_in[2];
    float*       out   = (float*)d_out;

    const int L = in_sizes[1];               // 100000
    const int B = in_sizes[0] / L;           // 512
    const int halfL = L / 2;

    npool_kernel<<<(halfL + 255) / 256, 256>>>(noise, halfL);

    size_t smem = (size_t)halfL * sizeof(float) + 66 * sizeof(float);
    cudaFuncSetAttribute(fused_kernel,
                         cudaFuncAttributeMaxDynamicSharedMemorySize,
                         (int)smem);
    fused_kernel<<<B, 1024, smem>>>(x, move, out, L);
}